// round 1
// baseline (speedup 1.0000x reference)
#include <cuda_runtime.h>
#include <math.h>

#define N_ATOMS 40000
#define N_BONDS 90000
#define MAX_NB 6
#define ATOM_FDIM 133
#define BOND_FDIM 147
#define HID 300
#define DEPTH 6
#define CAT_DIM (ATOM_FDIM + HID)   // 433

// ---------------- scratch (device globals; no cudaMalloc allowed) -------------
__device__ float g_inp [N_BONDS * HID];        // W_i output, also initial message
__device__ float g_gi  [N_BONDS * 3 * HID];    // precomputed input gates
__device__ float g_msg [N_BONDS * HID];        // current message
__device__ float g_h   [N_BONDS * HID];        // GRU hidden input per iter
__device__ float g_gh  [N_BONDS * 3 * HID];    // hidden gates
__device__ float g_amsg[N_ATOMS * HID];        // atom-aggregated message
__device__ float g_ain [N_ATOMS * CAT_DIM];    // concat(f_atoms, a_message)

// ---------------- generic TN SGEMM: C[m,n] = sum_k A[m,k]*B[n,k] (+bias,relu,mask)
#define BM 128
#define BN 128
#define BK 8
#define TM 8
#define TN 8

__global__ void sgemm_tn(const float* __restrict__ A, const float* __restrict__ B,
                         const float* __restrict__ bias, const float* __restrict__ mask,
                         float* __restrict__ C, int M, int N, int K, int relu)
{
    __shared__ float As[BK][BM];
    __shared__ float Bs[BK][BN];
    const int tid = threadIdx.x;               // 256 threads
    const int m0 = blockIdx.y * BM;
    const int n0 = blockIdx.x * BN;
    const int tx = tid & 15;                   // 16 along N
    const int ty = tid >> 4;                   // 16 along M

    float acc[TM][TN];
    #pragma unroll
    for (int i = 0; i < TM; i++)
        #pragma unroll
        for (int j = 0; j < TN; j++) acc[i][j] = 0.f;

    for (int k0 = 0; k0 < K; k0 += BK) {
        // load A tile (BM x BK), transposed into As[k][m]
        #pragma unroll
        for (int i = 0; i < 4; i++) {
            int idx = tid + i * 256;           // 0..1023
            int r = idx >> 3;                  // row in tile
            int kk = idx & 7;
            int gm = m0 + r, gk = k0 + kk;
            As[kk][r] = (gm < M && gk < K) ? A[(size_t)gm * K + gk] : 0.f;
        }
        // load B tile (BN x BK), transposed into Bs[k][n]
        #pragma unroll
        for (int i = 0; i < 4; i++) {
            int idx = tid + i * 256;
            int r = idx >> 3;
            int kk = idx & 7;
            int gn = n0 + r, gk = k0 + kk;
            Bs[kk][r] = (gn < N && gk < K) ? B[(size_t)gn * K + gk] : 0.f;
        }
        __syncthreads();

        #pragma unroll
        for (int kk = 0; kk < BK; kk++) {
            float a[TM], b[TN];
            #pragma unroll
            for (int i = 0; i < TM; i++) a[i] = As[kk][ty * TM + i];
            #pragma unroll
            for (int j = 0; j < TN; j++) b[j] = Bs[kk][tx * TN + j];
            #pragma unroll
            for (int i = 0; i < TM; i++)
                #pragma unroll
                for (int j = 0; j < TN; j++)
                    acc[i][j] = fmaf(a[i], b[j], acc[i][j]);
        }
        __syncthreads();
    }

    #pragma unroll
    for (int i = 0; i < TM; i++) {
        int gm = m0 + ty * TM + i;
        if (gm >= M) continue;
        #pragma unroll
        for (int j = 0; j < TN; j++) {
            int gn = n0 + tx * TN + j;
            if (gn >= N) continue;
            float v = acc[i][j];
            if (bias) v += bias[gn];
            if (relu) v = fmaxf(v, 0.f);
            if (mask) v *= mask[gm];
            C[(size_t)gm * N + gn] = v;
        }
    }
}

// ---------------- a_message[a,:] = sum_i message[a2b[a,i],:] -------------------
__global__ void gather_sum_kernel(const float* __restrict__ msg,
                                  const int* __restrict__ a2b,
                                  float* __restrict__ amsg)
{
    int idx = blockIdx.x * blockDim.x + threadIdx.x;
    if (idx >= N_ATOMS * HID) return;
    int a = idx / HID;
    int j = idx - a * HID;
    const int* nb = a2b + (size_t)a * MAX_NB;
    float s = 0.f;
    #pragma unroll
    for (int i = 0; i < MAX_NB; i++)
        s += msg[(size_t)nb[i] * HID + j];
    amsg[idx] = s;
}

// ---------------- h[b,:] = amsg[b2a[b],:] - msg[b2revb[b],:] -------------------
__global__ void hpre_kernel(const float* __restrict__ amsg,
                            const float* __restrict__ msg,
                            const int* __restrict__ b2a,
                            const int* __restrict__ b2revb,
                            float* __restrict__ h)
{
    int idx = blockIdx.x * blockDim.x + threadIdx.x;
    if (idx >= N_BONDS * HID) return;
    int b = idx / HID;
    int j = idx - b * HID;
    h[idx] = amsg[(size_t)b2a[b] * HID + j] - msg[(size_t)b2revb[b] * HID + j];
}

// ---------------- GRU elementwise, zero row 0 ----------------------------------
__device__ __forceinline__ float sigmoidf(float x) { return 1.f / (1.f + expf(-x)); }

__global__ void gru_kernel(const float* __restrict__ gi,
                           const float* __restrict__ gh,
                           const float* __restrict__ h,
                           float* __restrict__ out)
{
    int idx = blockIdx.x * blockDim.x + threadIdx.x;
    if (idx >= N_BONDS * HID) return;
    int b = idx / HID;
    int j = idx - b * HID;
    if (b == 0) { out[idx] = 0.f; return; }
    size_t base = (size_t)b * 3 * HID;
    float ir = gi[base + j], iz = gi[base + HID + j], in_ = gi[base + 2 * HID + j];
    float hr = gh[base + j], hz = gh[base + HID + j], hn  = gh[base + 2 * HID + j];
    float r = sigmoidf(ir + hr);
    float z = sigmoidf(iz + hz);
    float n = tanhf(in_ + r * hn);
    out[idx] = (1.f - z) * n + z * h[idx];
}

// ---------------- concat(f_atoms, amsg) -> ain ---------------------------------
__global__ void concat_kernel(const float* __restrict__ f_atoms,
                              const float* __restrict__ amsg,
                              float* __restrict__ ain)
{
    int idx = blockIdx.x * blockDim.x + threadIdx.x;
    if (idx >= N_ATOMS * CAT_DIM) return;
    int a = idx / CAT_DIM;
    int k = idx - a * CAT_DIM;
    ain[idx] = (k < ATOM_FDIM) ? f_atoms[(size_t)a * ATOM_FDIM + k]
                               : amsg[(size_t)a * HID + (k - ATOM_FDIM)];
}

// ---------------- launch --------------------------------------------------------
static inline dim3 gemm_grid(int M, int N) {
    return dim3((N + BN - 1) / BN, (M + BM - 1) / BM);
}

extern "C" void kernel_launch(void* const* d_in, const int* in_sizes, int n_in,
                              void* d_out, int out_size)
{
    const float* f_atoms = (const float*)d_in[0];
    const float* f_bonds = (const float*)d_in[1];
    const int*   a2b     = (const int*)  d_in[2];
    const int*   b2a     = (const int*)  d_in[3];
    const int*   b2revb  = (const int*)  d_in[4];
    // d_in[5] undirected_b2a, d_in[6] directed_b2a, d_in[7] parity_atoms: unused
    const float* mask    = (const float*)d_in[8];
    const float* W_i     = (const float*)d_in[9];   // [300,147]
    const float* W_ih    = (const float*)d_in[10];  // [900,300]
    const float* W_hh    = (const float*)d_in[11];  // [900,300]
    const float* b_ih    = (const float*)d_in[12];  // [900]
    const float* b_hh    = (const float*)d_in[13];  // [900]
    const float* W_o_w   = (const float*)d_in[14];  // [300,433]
    const float* W_o_b   = (const float*)d_in[15];  // [300]
    float* out = (float*)d_out;

    float *p_inp, *p_gi, *p_msg, *p_h, *p_gh, *p_amsg, *p_ain;
    cudaGetSymbolAddress((void**)&p_inp,  g_inp);
    cudaGetSymbolAddress((void**)&p_gi,   g_gi);
    cudaGetSymbolAddress((void**)&p_msg,  g_msg);
    cudaGetSymbolAddress((void**)&p_h,    g_h);
    cudaGetSymbolAddress((void**)&p_gh,   g_gh);
    cudaGetSymbolAddress((void**)&p_amsg, g_amsg);
    cudaGetSymbolAddress((void**)&p_ain,  g_ain);

    const int EW = 256;
    int nb_grid = (N_BONDS * HID + EW - 1) / EW;   // 90000*300
    int na_grid = (N_ATOMS * HID + EW - 1) / EW;
    int cat_grid = (N_ATOMS * CAT_DIM + EW - 1) / EW;

    // inp = f_bonds @ W_i^T
    sgemm_tn<<<gemm_grid(N_BONDS, HID), 256>>>(f_bonds, W_i, nullptr, nullptr,
                                               p_inp, N_BONDS, HID, BOND_FDIM, 0);
    // gi = inp @ W_ih^T + b_ih   (loop-invariant, computed once)
    sgemm_tn<<<gemm_grid(N_BONDS, 3 * HID), 256>>>(p_inp, W_ih, b_ih, nullptr,
                                                   p_gi, N_BONDS, 3 * HID, HID, 0);

    const float* msg_src = p_inp;   // initial message = inp
    for (int it = 0; it < DEPTH - 1; it++) {
        gather_sum_kernel<<<na_grid, EW>>>(msg_src, a2b, p_amsg);
        hpre_kernel<<<nb_grid, EW>>>(p_amsg, msg_src, b2a, b2revb, p_h);
        // gh = h @ W_hh^T + b_hh
        sgemm_tn<<<gemm_grid(N_BONDS, 3 * HID), 256>>>(p_h, W_hh, b_hh, nullptr,
                                                       p_gh, N_BONDS, 3 * HID, HID, 0);
        gru_kernel<<<nb_grid, EW>>>(p_gi, p_gh, p_h, p_msg);
        msg_src = p_msg;
    }

    gather_sum_kernel<<<na_grid, EW>>>(msg_src, a2b, p_amsg);
    concat_kernel<<<cat_grid, EW>>>(f_atoms, p_amsg, p_ain);
    // out = relu(ain @ W_o_w^T + W_o_b) * mask
    sgemm_tn<<<gemm_grid(N_ATOMS, HID), 256>>>(p_ain, W_o_w, W_o_b, mask,
                                               out, N_ATOMS, HID, CAT_DIM, 1);
}

// round 3
// speedup vs baseline: 1.8129x; 1.8129x over previous
#include <cuda_runtime.h>
#include <math.h>

#define N_ATOMS 40000
#define N_BONDS 90000
#define MAX_NB 6
#define ATOM_FDIM 133
#define BOND_FDIM 147
#define HID 300
#define DEPTH 6
#define CAT_DIM (ATOM_FDIM + HID)   // 433

#define H4   (HID / 4)              // 75
#define H34  (3 * HID / 4)          // 225

// ---------------- scratch (device globals; no cudaMalloc allowed) -------------
__device__ float g_inp [N_BONDS * HID];
__device__ float g_gi  [N_BONDS * 3 * HID];
__device__ float g_msg [N_BONDS * HID];
__device__ float g_h   [N_BONDS * HID];
__device__ float g_gh  [N_BONDS * 3 * HID];
__device__ float g_amsg[N_ATOMS * HID];
__device__ float g_ain [N_ATOMS * CAT_DIM];

// ================= 3xTF32 tensor-core TN GEMM ==================================
// C[m,n] = sum_k A[m,k] * B[n,k]  (+bias, relu, mask)
// Each operand split: x = hi + lo (hi = tf32-round(x)); C = hi*hi + hi*lo + lo*hi
#define BM 128
#define BN 128
#define BK 16
#define SPAD 20          // smem row stride in floats -> conflict-free fragment LDS

__device__ __forceinline__ unsigned smem_u32(const void* p) {
    return (unsigned)__cvta_generic_to_shared(p);
}
__device__ __forceinline__ void cp16(unsigned dst, const void* src) {
    asm volatile("cp.async.cg.shared.global [%0], [%1], 16;\n" :: "r"(dst), "l"(src));
}
__device__ __forceinline__ void cp4(unsigned dst, const void* src) {
    asm volatile("cp.async.ca.shared.global [%0], [%1], 4;\n" :: "r"(dst), "l"(src));
}
__device__ __forceinline__ void cp_commit() { asm volatile("cp.async.commit_group;\n"); }
__device__ __forceinline__ void cp_wait0()  { asm volatile("cp.async.wait_group 0;\n"); }
__device__ __forceinline__ void sts_zero16(unsigned dst) {
    asm volatile("st.shared.v4.b32 [%0], {%1,%1,%1,%1};" :: "r"(dst), "r"(0));
}
__device__ __forceinline__ void sts_zero4(unsigned dst) {
    asm volatile("st.shared.b32 [%0], %1;" :: "r"(dst), "r"(0));
}
__device__ __forceinline__ void mma_tf32(float* c, const unsigned* a, const unsigned* b) {
    asm volatile(
        "mma.sync.aligned.m16n8k8.row.col.f32.tf32.tf32.f32 "
        "{%0,%1,%2,%3},{%4,%5,%6,%7},{%8,%9},{%0,%1,%2,%3};"
        : "+f"(c[0]), "+f"(c[1]), "+f"(c[2]), "+f"(c[3])
        : "r"(a[0]), "r"(a[1]), "r"(a[2]), "r"(a[3]), "r"(b[0]), "r"(b[1]));
}
// split fp32 -> (hi tf32, lo tf32)
__device__ __forceinline__ void tf32_split(float v, unsigned& hi, unsigned& lo) {
    asm("cvt.rna.tf32.f32 %0, %1;" : "=r"(hi) : "f"(v));
    float l = v - __uint_as_float(hi);
    asm("cvt.rna.tf32.f32 %0, %1;" : "=r"(lo) : "f"(l));
}

__global__ void __launch_bounds__(256)
mma_gemm_tn(const float* __restrict__ A, const float* __restrict__ B,
            const float* __restrict__ bias, const float* __restrict__ mask,
            float* __restrict__ C, int M, int N, int K, int relu)
{
    __shared__ float As[2][BM][SPAD];
    __shared__ float Bs[2][BN][SPAD];

    const int tid  = threadIdx.x;
    const int wid  = tid >> 5;
    const int lane = tid & 31;
    const int g = lane >> 2, t = lane & 3;
    const int warp_m = wid & 1;     // 2 warps along M (64 rows each)
    const int warp_n = wid >> 1;    // 4 warps along N (32 cols each)
    const int m0 = blockIdx.y * BM;
    const int n0 = blockIdx.x * BN;
    const int KT = (K + BK - 1) / BK;
    const bool vec = ((K & 3) == 0);

    float acc[4][4][4];
    #pragma unroll
    for (int mi = 0; mi < 4; mi++)
        #pragma unroll
        for (int ni = 0; ni < 4; ni++)
            #pragma unroll
            for (int r = 0; r < 4; r++) acc[mi][ni][r] = 0.f;

    auto load_tile = [&](int kt, int s) {
        const int k0 = kt * BK;
        unsigned abase = smem_u32(&As[s][0][0]);
        unsigned bbase = smem_u32(&Bs[s][0][0]);
        if (vec) {
            #pragma unroll
            for (int i = 0; i < 2; i++) {
                int idx = tid + i * 256;
                int row = idx >> 2;
                int seg = idx & 3;
                int gk  = k0 + seg * 4;
                unsigned da = abase + (unsigned)(row * SPAD + seg * 4) * 4u;
                unsigned db = bbase + (unsigned)(row * SPAD + seg * 4) * 4u;
                int gm = m0 + row, gn = n0 + row;
                if (gm < M && gk < K) cp16(da, A + (size_t)gm * K + gk);
                else                  sts_zero16(da);
                if (gn < N && gk < K) cp16(db, B + (size_t)gn * K + gk);
                else                  sts_zero16(db);
            }
        } else {
            #pragma unroll
            for (int i = 0; i < 8; i++) {
                int idx = tid + i * 256;
                int row = idx >> 4;
                int kk  = idx & 15;
                int gk  = k0 + kk;
                unsigned da = abase + (unsigned)(row * SPAD + kk) * 4u;
                unsigned db = bbase + (unsigned)(row * SPAD + kk) * 4u;
                int gm = m0 + row, gn = n0 + row;
                if (gm < M && gk < K) cp4(da, A + (size_t)gm * K + gk);
                else                  sts_zero4(da);
                if (gn < N && gk < K) cp4(db, B + (size_t)gn * K + gk);
                else                  sts_zero4(db);
            }
        }
    };

    load_tile(0, 0);
    cp_commit();

    for (int kt = 0; kt < KT; kt++) {
        cp_wait0();
        __syncthreads();
        const int cur = kt & 1;
        if (kt + 1 < KT) load_tile(kt + 1, cur ^ 1);
        cp_commit();

        #pragma unroll
        for (int kk = 0; kk < BK; kk += 8) {
            unsigned ah[4][4], al[4][4], bh[4][2], bl[4][2];
            #pragma unroll
            for (int mi = 0; mi < 4; mi++) {
                int m = warp_m * 64 + mi * 16;
                tf32_split(As[cur][m + g     ][kk + t    ], ah[mi][0], al[mi][0]);
                tf32_split(As[cur][m + g + 8 ][kk + t    ], ah[mi][1], al[mi][1]);
                tf32_split(As[cur][m + g     ][kk + t + 4], ah[mi][2], al[mi][2]);
                tf32_split(As[cur][m + g + 8 ][kk + t + 4], ah[mi][3], al[mi][3]);
            }
            #pragma unroll
            for (int ni = 0; ni < 4; ni++) {
                int n = warp_n * 32 + ni * 8;
                tf32_split(Bs[cur][n + g][kk + t    ], bh[ni][0], bl[ni][0]);
                tf32_split(Bs[cur][n + g][kk + t + 4], bh[ni][1], bl[ni][1]);
            }
            #pragma unroll
            for (int mi = 0; mi < 4; mi++)
                #pragma unroll
                for (int ni = 0; ni < 4; ni++) {
                    mma_tf32(acc[mi][ni], al[mi], bh[ni]);   // lo*hi
                    mma_tf32(acc[mi][ni], ah[mi], bl[ni]);   // hi*lo
                    mma_tf32(acc[mi][ni], ah[mi], bh[ni]);   // hi*hi (largest last)
                }
        }
    }

    // epilogue
    #pragma unroll
    for (int mi = 0; mi < 4; mi++) {
        #pragma unroll
        for (int ni = 0; ni < 4; ni++) {
            int cn = n0 + warp_n * 32 + ni * 8 + 2 * t;
            float b0 = 0.f, b1 = 0.f;
            if (bias) {
                if (cn     < N) b0 = bias[cn];
                if (cn + 1 < N) b1 = bias[cn + 1];
            }
            #pragma unroll
            for (int half = 0; half < 2; half++) {
                int rm = m0 + warp_m * 64 + mi * 16 + g + half * 8;
                if (rm >= M) continue;
                float v0 = acc[mi][ni][half * 2 + 0] + b0;
                float v1 = acc[mi][ni][half * 2 + 1] + b1;
                if (relu) { v0 = fmaxf(v0, 0.f); v1 = fmaxf(v1, 0.f); }
                if (mask) { float mk = mask[rm]; v0 *= mk; v1 *= mk; }
                if (cn + 1 < N) {
                    float2 v = {v0, v1};
                    *(float2*)(C + (size_t)rm * N + cn) = v;
                } else if (cn < N) {
                    C[(size_t)rm * N + cn] = v0;
                }
            }
        }
    }
}

// ================= elementwise (float4) =========================================
__global__ void gather_sum4(const float4* __restrict__ msg,
                            const int* __restrict__ a2b,
                            float4* __restrict__ amsg)
{
    int idx = blockIdx.x * blockDim.x + threadIdx.x;
    if (idx >= N_ATOMS * H4) return;
    int a = idx / H4;
    int j = idx - a * H4;
    const int* nb = a2b + (size_t)a * MAX_NB;
    float4 s = {0.f, 0.f, 0.f, 0.f};
    #pragma unroll
    for (int i = 0; i < MAX_NB; i++) {
        float4 v = msg[(size_t)nb[i] * H4 + j];
        s.x += v.x; s.y += v.y; s.z += v.z; s.w += v.w;
    }
    amsg[idx] = s;
}

__global__ void hpre4(const float4* __restrict__ amsg,
                      const float4* __restrict__ msg,
                      const int* __restrict__ b2a,
                      const int* __restrict__ b2revb,
                      float4* __restrict__ h)
{
    int idx = blockIdx.x * blockDim.x + threadIdx.x;
    if (idx >= N_BONDS * H4) return;
    int b = idx / H4;
    int j = idx - b * H4;
    float4 u = amsg[(size_t)b2a[b] * H4 + j];
    float4 v = msg[(size_t)b2revb[b] * H4 + j];
    float4 o = {u.x - v.x, u.y - v.y, u.z - v.z, u.w - v.w};
    h[idx] = o;
}

__device__ __forceinline__ float sigmoidf1(float x) { return 1.f / (1.f + expf(-x)); }

__global__ void gru4(const float4* __restrict__ gi,
                     const float4* __restrict__ gh,
                     const float4* __restrict__ h,
                     float4* __restrict__ out)
{
    int idx = blockIdx.x * blockDim.x + threadIdx.x;
    if (idx >= N_BONDS * H4) return;
    int b = idx / H4;
    int j = idx - b * H4;
    if (b == 0) { out[idx] = make_float4(0.f, 0.f, 0.f, 0.f); return; }
    size_t gb = (size_t)b * H34;
    float4 ir = gi[gb + j], iz = gi[gb + H4 + j], in4 = gi[gb + 2 * H4 + j];
    float4 hr = gh[gb + j], hz = gh[gb + H4 + j], hn4 = gh[gb + 2 * H4 + j];
    float4 hh = h[idx];
    float4 o;
    {
        float r = sigmoidf1(ir.x + hr.x), z = sigmoidf1(iz.x + hz.x);
        float n = tanhf(in4.x + r * hn4.x);
        o.x = (1.f - z) * n + z * hh.x;
    }
    {
        float r = sigmoidf1(ir.y + hr.y), z = sigmoidf1(iz.y + hz.y);
        float n = tanhf(in4.y + r * hn4.y);
        o.y = (1.f - z) * n + z * hh.y;
    }
    {
        float r = sigmoidf1(ir.z + hr.z), z = sigmoidf1(iz.z + hz.z);
        float n = tanhf(in4.z + r * hn4.z);
        o.z = (1.f - z) * n + z * hh.z;
    }
    {
        float r = sigmoidf1(ir.w + hr.w), z = sigmoidf1(iz.w + hz.w);
        float n = tanhf(in4.w + r * hn4.w);
        o.w = (1.f - z) * n + z * hh.w;
    }
    out[idx] = o;
}

__global__ void concat_kernel(const float* __restrict__ f_atoms,
                              const float* __restrict__ amsg,
                              float* __restrict__ ain)
{
    int idx = blockIdx.x * blockDim.x + threadIdx.x;
    if (idx >= N_ATOMS * CAT_DIM) return;
    int a = idx / CAT_DIM;
    int k = idx - a * CAT_DIM;
    ain[idx] = (k < ATOM_FDIM) ? f_atoms[(size_t)a * ATOM_FDIM + k]
                               : amsg[(size_t)a * HID + (k - ATOM_FDIM)];
}

// ================= launch ========================================================
static inline dim3 gemm_grid(int M, int N) {
    return dim3((N + BN - 1) / BN, (M + BM - 1) / BM);
}

extern "C" void kernel_launch(void* const* d_in, const int* in_sizes, int n_in,
                              void* d_out, int out_size)
{
    const float* f_atoms = (const float*)d_in[0];
    const float* f_bonds = (const float*)d_in[1];
    const int*   a2b     = (const int*)  d_in[2];
    const int*   b2a     = (const int*)  d_in[3];
    const int*   b2revb  = (const int*)  d_in[4];
    const float* mask    = (const float*)d_in[8];
    const float* W_i     = (const float*)d_in[9];   // [300,147]
    const float* W_ih    = (const float*)d_in[10];  // [900,300]
    const float* W_hh    = (const float*)d_in[11];  // [900,300]
    const float* b_ih    = (const float*)d_in[12];
    const float* b_hh    = (const float*)d_in[13];
    const float* W_o_w   = (const float*)d_in[14];  // [300,433]
    const float* W_o_b   = (const float*)d_in[15];
    float* out = (float*)d_out;

    float *p_inp, *p_gi, *p_msg, *p_h, *p_gh, *p_amsg, *p_ain;
    cudaGetSymbolAddress((void**)&p_inp,  g_inp);
    cudaGetSymbolAddress((void**)&p_gi,   g_gi);
    cudaGetSymbolAddress((void**)&p_msg,  g_msg);
    cudaGetSymbolAddress((void**)&p_h,    g_h);
    cudaGetSymbolAddress((void**)&p_gh,   g_gh);
    cudaGetSymbolAddress((void**)&p_amsg, g_amsg);
    cudaGetSymbolAddress((void**)&p_ain,  g_ain);

    const int EW = 256;
    int nb4_grid = (N_BONDS * H4 + EW - 1) / EW;
    int na4_grid = (N_ATOMS * H4 + EW - 1) / EW;
    int cat_grid = (N_ATOMS * CAT_DIM + EW - 1) / EW;

    // inp = f_bonds @ W_i^T            [90000,300] K=147
    mma_gemm_tn<<<gemm_grid(N_BONDS, HID), 256>>>(f_bonds, W_i, nullptr, nullptr,
                                                  p_inp, N_BONDS, HID, BOND_FDIM, 0);
    // gi = inp @ W_ih^T + b_ih         [90000,900] K=300  (loop-invariant)
    mma_gemm_tn<<<gemm_grid(N_BONDS, 3 * HID), 256>>>(p_inp, W_ih, b_ih, nullptr,
                                                      p_gi, N_BONDS, 3 * HID, HID, 0);

    const float* msg_src = p_inp;
    for (int it = 0; it < DEPTH - 1; it++) {
        gather_sum4<<<na4_grid, EW>>>((const float4*)msg_src, a2b, (float4*)p_amsg);
        hpre4<<<nb4_grid, EW>>>((const float4*)p_amsg, (const float4*)msg_src,
                                b2a, b2revb, (float4*)p_h);
        // gh = h @ W_hh^T + b_hh       [90000,900] K=300
        mma_gemm_tn<<<gemm_grid(N_BONDS, 3 * HID), 256>>>(p_h, W_hh, b_hh, nullptr,
                                                          p_gh, N_BONDS, 3 * HID, HID, 0);
        gru4<<<nb4_grid, EW>>>((const float4*)p_gi, (const float4*)p_gh,
                               (const float4*)p_h, (float4*)p_msg);
        msg_src = p_msg;
    }

    gather_sum4<<<na4_grid, EW>>>((const float4*)msg_src, a2b, (float4*)p_amsg);
    concat_kernel<<<cat_grid, EW>>>(f_atoms, p_amsg, p_ain);
    // out = relu(ain @ W_o_w^T + W_o_b) * mask   [40000,300] K=433
    mma_gemm_tn<<<gemm_grid(N_ATOMS, HID), 256>>>(p_ain, W_o_w, W_o_b, mask,
                                                  out, N_ATOMS, HID, CAT_DIM, 1);
}